// round 1
// baseline (speedup 1.0000x reference)
#include <cuda_runtime.h>

#define TSEQ 4096
#define HID  1024
#define NH   16
#define HD   64

// Scratch for Q, K, V in [head][token][dh] layout (16 MB each).
__device__ float g_q[NH * TSEQ * HD];
__device__ float g_k[NH * TSEQ * HD];
__device__ float g_v[NH * TSEQ * HD];

// ---------------------------------------------------------------------------
// Kernel 1: QKV GEMM.  C[4096, 3072] = x[4096,1024] @ W[1024,3072]
// 64x64 output tile per block, BK=16, 256 threads, 4x4 fragment per thread.
// Output column n maps to (s, h, d) = (n/1024, (n%1024)/64, n%64); each 64-wide
// N-tile lands entirely in one of Q/K/V for one head -> contiguous writeout.
// ---------------------------------------------------------------------------
__global__ __launch_bounds__(256) void qkv_gemm_kernel(const float* __restrict__ x,
                                                       const float* __restrict__ W) {
    __shared__ float As[16][68];   // transposed: As[k][m]
    __shared__ float Bs[16][68];   // Bs[k][n]

    const int tid = threadIdx.x;
    const int tx = tid & 15, ty = tid >> 4;
    const int n0 = blockIdx.x * 64;
    const int m0 = blockIdx.y * 64;

    const int arow = tid >> 2;            // 0..63
    const int acol = (tid & 3) << 2;      // 0,4,8,12
    const int brow = tid >> 4;            // 0..15
    const int bcol = (tid & 15) << 2;     // 0..60

    float acc[4][4] = {};

    for (int k0 = 0; k0 < HID; k0 += 16) {
        float4 av = *(const float4*)&x[(m0 + arow) * HID + k0 + acol];
        As[acol + 0][arow] = av.x;
        As[acol + 1][arow] = av.y;
        As[acol + 2][arow] = av.z;
        As[acol + 3][arow] = av.w;
        *(float4*)&Bs[brow][bcol] =
            *(const float4*)&W[(k0 + brow) * (3 * HID) + n0 + bcol];
        __syncthreads();

#pragma unroll
        for (int kk = 0; kk < 16; kk++) {
            float4 a = *(float4*)&As[kk][ty << 2];
            float4 b = *(float4*)&Bs[kk][tx << 2];
            float ar[4] = {a.x, a.y, a.z, a.w};
            float br[4] = {b.x, b.y, b.z, b.w};
#pragma unroll
            for (int i = 0; i < 4; i++)
#pragma unroll
                for (int j = 0; j < 4; j++) acc[i][j] += ar[i] * br[j];
        }
        __syncthreads();
    }

    const int s = n0 / HID;
    const int h = (n0 % HID) / HD;
    float* dst = (s == 0) ? g_q : (s == 1) ? g_k : g_v;

#pragma unroll
    for (int i = 0; i < 4; i++) {
        const int t = m0 + (ty << 2) + i;
        *(float4*)&dst[(h * TSEQ + t) * HD + (tx << 2)] =
            make_float4(acc[i][0], acc[i][1], acc[i][2], acc[i][3]);
    }
}

// ---------------------------------------------------------------------------
// Kernel 2: flash attention.  One block per (64-query tile, head).
// Q,K tiles stored transposed [d][r] so the QK^T inner loop reads are
// broadcast (Q) + contiguous float4 (K).  S stored [c][r] so the PV loop
// reads are contiguous float4 too.  Online softmax (m, l, corr per row).
// ---------------------------------------------------------------------------
#define STR 68
#define ATTN_SMEM_BYTES ((4 * 64 * STR + 3 * 64) * 4)

__global__ __launch_bounds__(256) void flash_attn_kernel(float* __restrict__ out) {
    extern __shared__ float sm[];
    float* Qs   = sm;                // [d][r]   64 x STR
    float* Ks   = Qs + 64 * STR;     // [d][c]   64 x STR
    float* Vs   = Ks + 64 * STR;     // [k][d]   64 x STR
    float* Ss   = Vs + 64 * STR;     // [c][r]   64 x STR
    float* mrow = Ss + 64 * STR;     // [64]
    float* lrow = mrow + 64;         // [64]
    float* corr = lrow + 64;         // [64]

    const int tid = threadIdx.x;
    const int tx = tid & 15, ty = tid >> 4;
    const int h  = blockIdx.y;
    const int q0 = blockIdx.x * 64;
    const float scale = 0.125f;      // 1/sqrt(64)

    const float* Qg = g_q + h * TSEQ * HD;
    const float* Kg = g_k + h * TSEQ * HD;
    const float* Vg = g_v + h * TSEQ * HD;

    const int lr  = tid >> 2;          // row handled by this thread in load/softmax
    const int ld0 = (tid & 3) << 4;    // 16-wide segment

    // Load Q tile transposed into Qs[d][r]
#pragma unroll
    for (int c = 0; c < 4; c++) {
        const int d = ld0 + c * 4;
        float4 v = *(const float4*)&Qg[(q0 + lr) * HD + d];
        Qs[(d + 0) * STR + lr] = v.x;
        Qs[(d + 1) * STR + lr] = v.y;
        Qs[(d + 2) * STR + lr] = v.z;
        Qs[(d + 3) * STR + lr] = v.w;
    }
    if (tid < 64) { mrow[tid] = -1e30f; lrow[tid] = 0.f; }

    float o[4][4] = {};

    for (int kb = 0; kb < TSEQ / 64; kb++) {
        const int c0 = kb * 64;
        __syncthreads();   // protect Ks/Vs/Ss vs previous iteration; Q/m/l init on iter 0

        // Load K transposed [d][c], V natural [k][d]
#pragma unroll
        for (int c = 0; c < 4; c++) {
            const int d = ld0 + c * 4;
            float4 kv = *(const float4*)&Kg[(c0 + lr) * HD + d];
            Ks[(d + 0) * STR + lr] = kv.x;
            Ks[(d + 1) * STR + lr] = kv.y;
            Ks[(d + 2) * STR + lr] = kv.z;
            Ks[(d + 3) * STR + lr] = kv.w;
            *(float4*)&Vs[lr * STR + d] = *(const float4*)&Vg[(c0 + lr) * HD + d];
        }
        __syncthreads();

        // S = Q @ K^T  (fragment: rows ty*4.., key cols tx*4..)
        float s[4][4] = {};
#pragma unroll
        for (int d = 0; d < 64; d++) {
            float4 a = *(float4*)&Qs[d * STR + (ty << 2)];
            float4 b = *(float4*)&Ks[d * STR + (tx << 2)];
            float ar[4] = {a.x, a.y, a.z, a.w};
            float br[4] = {b.x, b.y, b.z, b.w};
#pragma unroll
            for (int i = 0; i < 4; i++)
#pragma unroll
                for (int j = 0; j < 4; j++) s[i][j] += ar[i] * br[j];
        }
        // Write S transposed: Ss[c][r] = s[r][c] * scale (float4 along r)
#pragma unroll
        for (int j = 0; j < 4; j++) {
            *(float4*)&Ss[((tx << 2) + j) * STR + (ty << 2)] =
                make_float4(s[0][j] * scale, s[1][j] * scale,
                            s[2][j] * scale, s[3][j] * scale);
        }
        __syncthreads();

        // Online softmax: 4 threads per row, 16 keys each
        {
            float mloc = -1e30f;
#pragma unroll
            for (int c = 0; c < 16; c++)
                mloc = fmaxf(mloc, Ss[(ld0 + c) * STR + lr]);
            mloc = fmaxf(mloc, __shfl_xor_sync(0xffffffffu, mloc, 1));
            mloc = fmaxf(mloc, __shfl_xor_sync(0xffffffffu, mloc, 2));
            const float mold = mrow[lr];
            const float mnew = fmaxf(mold, mloc);
            float sum = 0.f;
#pragma unroll
            for (int c = 0; c < 16; c++) {
                const float p = __expf(Ss[(ld0 + c) * STR + lr] - mnew);
                Ss[(ld0 + c) * STR + lr] = p;
                sum += p;
            }
            sum += __shfl_xor_sync(0xffffffffu, sum, 1);
            sum += __shfl_xor_sync(0xffffffffu, sum, 2);
            if ((tid & 3) == 0) {
                const float cf = __expf(mold - mnew);
                corr[lr] = cf;
                lrow[lr] = lrow[lr] * cf + sum;
                mrow[lr] = mnew;
            }
        }
        __syncthreads();

        // Rescale O, then O += P @ V
#pragma unroll
        for (int i = 0; i < 4; i++) {
            const float cf = corr[(ty << 2) + i];
#pragma unroll
            for (int j = 0; j < 4; j++) o[i][j] *= cf;
        }
#pragma unroll
        for (int kk = 0; kk < 64; kk++) {
            float4 p = *(float4*)&Ss[kk * STR + (ty << 2)];   // P[r..r+3][kk]
            float4 v = *(float4*)&Vs[kk * STR + (tx << 2)];   // V[kk][d..d+3]
            float pr[4] = {p.x, p.y, p.z, p.w};
            float vr[4] = {v.x, v.y, v.z, v.w};
#pragma unroll
            for (int i = 0; i < 4; i++)
#pragma unroll
                for (int j = 0; j < 4; j++) o[i][j] += pr[i] * vr[j];
        }
    }

    // Normalize and write out[t][h*64 + d]
#pragma unroll
    for (int i = 0; i < 4; i++) {
        const int t = q0 + (ty << 2) + i;
        const float inv = 1.f / lrow[(ty << 2) + i];
        *(float4*)&out[t * HID + h * HD + (tx << 2)] =
            make_float4(o[i][0] * inv, o[i][1] * inv, o[i][2] * inv, o[i][3] * inv);
    }
}

// ---------------------------------------------------------------------------
extern "C" void kernel_launch(void* const* d_in, const int* in_sizes, int n_in,
                              void* d_out, int out_size) {
    const float* x = (const float*)d_in[0];       // [1, 4096, 1024] fp32
    const float* W = (const float*)d_in[1];       // [1024, 3072]  fp32
    float* out = (float*)d_out;                   // [1, 4096, 1024] fp32

    dim3 ggrid(3 * HID / 64, TSEQ / 64);          // (48, 64)
    qkv_gemm_kernel<<<ggrid, 256>>>(x, W);

    cudaFuncSetAttribute(flash_attn_kernel,
                         cudaFuncAttributeMaxDynamicSharedMemorySize,
                         ATTN_SMEM_BYTES);
    dim3 agrid(TSEQ / 64, NH);                    // (64, 16)
    flash_attn_kernel<<<agrid, 256, ATTN_SMEM_BYTES>>>(out);
}